// round 6
// baseline (speedup 1.0000x reference)
#include <cuda_runtime.h>

// ResidualDenseBlock: out = scan_{l=0..63}( tanh(out @ W[l]^T + b[l]) * m[l] + out ) * sum(gates)
//
// R5b: XU(MUFU)-bound at 6 tanh insts/layer (4x f32 + 2x f16x2 covering 4 rows' 8 tanhs).
// f16->f32 unpack done with exact ALU bit tricks + 2^112 magic scale folded into the
// mask constant (m112 = m * 2^112), so NO cvt.f32.f16 instructions touch the XU pipe.

#define LAYERS  64
#define TPB     256

__device__ __forceinline__ float tanh_f32(float x) {
    float y;
    asm("tanh.approx.f32 %0, %1;" : "=f"(y) : "f"(x));
    return y;
}
__device__ __forceinline__ unsigned tanh_h2(unsigned h) {
    unsigned r;
    asm("tanh.approx.f16x2 %0, %1;" : "=r"(r) : "r"(h));
    return r;
}
// d = { hi = cvt(a), lo = cvt(b) }
__device__ __forceinline__ unsigned pack_h2(float hi, float lo) {
    unsigned r;
    asm("cvt.rn.f16x2.f32 %0, %1, %2;" : "=r"(r) : "f"(hi), "f"(lo));
    return r;
}
// Exact f16 -> f32*2^-112 reinterpretation (ALU only, no XU cvt).
// lo half: sign bit15 -> bit31, exp+mant bits[14:0] -> bits[27:13]:
//   (r<<16 & 0x80000000) | (r<<13 & 0x0FFFE000)  -- 2 shifts + 1 LOP3
__device__ __forceinline__ float mag_lo(unsigned r) {
    unsigned s = r << 16;          // sign at bit31
    unsigned e = r << 13;          // exp+mant at bits[27:13]
    unsigned b;
    asm("lop3.b32 %0, %1, 0x80000000, %2, 0xEA;"   // (s & 0x80000000) | (e & ~0x80000000 masked below)
        : "=r"(b) : "r"(s), "r"(e & 0x0FFFE000u));
    return __uint_as_float(b);
}
// hi half: sign already at bit31; bits[30:16] -> bits[27:13] via >>3.
__device__ __forceinline__ float mag_hi(unsigned r) {
    unsigned e = r >> 3;
    unsigned b;
    asm("lop3.b32 %0, %1, 0x80000000, %2, 0xEA;"
        : "=r"(b) : "r"(r), "r"(e & 0x0FFFE000u));
    return __uint_as_float(b);
}

__global__ __launch_bounds__(TPB)
void rdb_kernel(const float4* __restrict__ x,
                const float*  __restrict__ W,
                const float*  __restrict__ b,
                const float*  __restrict__ masks,
                const float*  __restrict__ gates,
                float4* __restrict__ out,
                long long nfloat4)
{
    __shared__ float4 sW[LAYERS];   // w00, w01, w10, w11
    __shared__ float4 sB[LAYERS];   // b0, b1, m, m*2^112
    __shared__ float  sG;

    const int tid = threadIdx.x;
    if (tid < LAYERS) {
        sW[tid] = make_float4(W[tid * 4 + 0], W[tid * 4 + 1],
                              W[tid * 4 + 2], W[tid * 4 + 3]);
        float m = masks[tid];
        sB[tid] = make_float4(b[tid * 2 + 0], b[tid * 2 + 1],
                              m, m * 0x1p112f);
    }
    if (tid == 0) {
        float s = 0.0f;
        #pragma unroll
        for (int i = 0; i < LAYERS; i++) s += gates[i];
        sG = s;
    }
    __syncthreads();

    const long long gt = (long long)blockIdx.x * TPB + tid;
    const long long f4base = gt * 2;
    if (f4base >= nfloat4) return;
    const bool have2 = (f4base + 1) < nfloat4;

    float4 A = x[f4base];                                    // rows 0,1
    float4 C = have2 ? x[f4base + 1] : make_float4(0,0,0,0); // rows 2,3

    float x0 = A.x, y0 = A.y, x1 = A.z, y1 = A.w;
    float x2 = C.x, y2 = C.y, x3 = C.z, y3 = C.w;

    #pragma unroll 8
    for (int l = 0; l < LAYERS; l++) {
        const float4 w = sW[l];
        const float4 p = sB[l];   // p.z = m, p.w = m*2^112

        // ---- rows 0,1: exact f32 tanh ----
        float a0 = fmaf(w.x, x0, fmaf(w.y, y0, p.x));
        float a1 = fmaf(w.z, x0, fmaf(w.w, y0, p.y));
        float a2 = fmaf(w.x, x1, fmaf(w.y, y1, p.x));
        float a3 = fmaf(w.z, x1, fmaf(w.w, y1, p.y));

        // ---- rows 2,3: pre-activations ----
        float c0 = fmaf(w.x, x2, fmaf(w.y, y2, p.x));
        float c1 = fmaf(w.z, x2, fmaf(w.w, y2, p.y));
        float c2 = fmaf(w.x, x3, fmaf(w.y, y3, p.x));
        float c3 = fmaf(w.z, x3, fmaf(w.w, y3, p.y));

        // issue all 6 XU ops back-to-back (independent chains)
        float t0 = tanh_f32(a0);
        float t1 = tanh_f32(a1);
        float t2 = tanh_f32(a2);
        float t3 = tanh_f32(a3);
        unsigned hA = tanh_h2(pack_h2(c2, c0));  // lo=row2.x, hi=row3.x
        unsigned hB = tanh_h2(pack_h2(c3, c1));  // lo=row2.y, hi=row3.y

        x0 = fmaf(p.z, t0, x0);
        y0 = fmaf(p.z, t1, y0);
        x1 = fmaf(p.z, t2, x1);
        y1 = fmaf(p.z, t3, y1);

        // residual: state += (tanh16 * 2^-112) * (m * 2^112) -- single rounding
        x2 = fmaf(mag_lo(hA), p.w, x2);
        x3 = fmaf(mag_hi(hA), p.w, x3);
        y2 = fmaf(mag_lo(hB), p.w, y2);
        y3 = fmaf(mag_hi(hB), p.w, y3);
    }

    const float g = sG;
    out[f4base] = make_float4(g * x0, g * y0, g * x1, g * y1);
    if (have2)
        out[f4base + 1] = make_float4(g * x2, g * y2, g * x3, g * y3);
}

extern "C" void kernel_launch(void* const* d_in, const int* in_sizes, int n_in,
                              void* d_out, int out_size)
{
    const float4* x     = (const float4*)d_in[0];
    const float*  W     = (const float*) d_in[1];
    const float*  b     = (const float*) d_in[2];
    const float*  masks = (const float*) d_in[3];
    const float*  gates = (const float*) d_in[4];
    float4* out = (float4*)d_out;

    const long long nfloat  = (long long)in_sizes[0];   // BATCH * 2
    const long long nfloat4 = nfloat / 4;               // BATCH / 2
    const long long threads = (nfloat4 + 1) / 2;
    const int blocks = (int)((threads + TPB - 1) / TPB);
    rdb_kernel<<<blocks, TPB>>>(x, W, b, masks, gates, out, nfloat4);
}

// round 7
// speedup vs baseline: 1.0189x; 1.0189x over previous
#include <cuda_runtime.h>

// ResidualDenseBlock: out = scan_{l=0..63}( tanh(out @ W[l]^T + b[l]) * m[l] + out ) * sum(gates)
//
// R7 = R4 + ALU mag-unpack (controlled experiment):
//  - rows 0,1: exact tanh.approx.f32 (4 MUFU)
//  - rows 2,3: tanh.approx.f16x2 (2 MUFU, full-rate per R5b evidence)
//  - all layer math: packed fma.rn.f32x2 (12 FFMA2/layer) -- as in R4 (133us)
//  - f16->f32 unpack: exact bit-shift to f32*2^-112 on ALU pipe, compensated by
//    m112 = m * 2^112 folded into the layer constants (bit-identical, proven in R5b).
//  No cvt.f32.f16 instructions -> XU pipe carries ONLY the 6 tanh ops (48 cyc).

#define LAYERS  64
#define TPB     256

typedef unsigned long long u64;

__device__ __forceinline__ float tanh_f32(float x) {
    float y;
    asm("tanh.approx.f32 %0, %1;" : "=f"(y) : "f"(x));
    return y;
}
__device__ __forceinline__ unsigned tanh_h2(unsigned h) {
    unsigned r;
    asm("tanh.approx.f16x2 %0, %1;" : "=r"(r) : "r"(h));
    return r;
}
// d = { hi = cvt(%1), lo = cvt(%2) }
__device__ __forceinline__ unsigned pack_h2(float hi, float lo) {
    unsigned r;
    asm("cvt.rn.f16x2.f32 %0, %1, %2;" : "=r"(r) : "f"(hi), "f"(lo));
    return r;
}
// Exact f16 -> f32*2^-112 reinterpretation (ALU only).
// lo half: sign bit15 -> bit31; exp+mant bits[14:0] -> bits[27:13].
__device__ __forceinline__ float mag_lo(unsigned r) {
    unsigned b = ((r << 16) & 0x80000000u) | ((r << 13) & 0x0FFFE000u);
    return __uint_as_float(b);
}
// hi half: sign already at bit31; bits[30:16] -> bits[27:13] via >>3.
__device__ __forceinline__ float mag_hi(unsigned r) {
    unsigned b = (r & 0x80000000u) | ((r >> 3) & 0x0FFFE000u);
    return __uint_as_float(b);
}
__device__ __forceinline__ u64 fma2(u64 a, u64 b, u64 c) {
    u64 d;
    asm("fma.rn.f32x2 %0, %1, %2, %3;" : "=l"(d) : "l"(a), "l"(b), "l"(c));
    return d;
}
__device__ __forceinline__ u64 mul2(u64 a, u64 b) {
    u64 d;
    asm("mul.rn.f32x2 %0, %1, %2;" : "=l"(d) : "l"(a), "l"(b));
    return d;
}
__device__ __forceinline__ u64 pk2(float lo, float hi) {
    u64 d;
    asm("mov.b64 %0, {%1, %2};" : "=l"(d) : "f"(lo), "f"(hi));
    return d;
}
__device__ __forceinline__ void up2(float& lo, float& hi, u64 s) {
    asm("mov.b64 {%0, %1}, %2;" : "=f"(lo), "=f"(hi) : "l"(s));
}

struct __align__(16) LayerP {
    u64 w00, w01, w10, w11, b0, b1, m, m112;  // broadcast (v,v) pairs; m112 = m*2^112
};

__global__ __launch_bounds__(TPB)
void rdb_kernel(const float4* __restrict__ x,
                const float*  __restrict__ W,
                const float*  __restrict__ b,
                const float*  __restrict__ masks,
                const float*  __restrict__ gates,
                float4* __restrict__ out,
                long long nfloat4)
{
    __shared__ LayerP sP[LAYERS];
    __shared__ float  sG;

    const int tid = threadIdx.x;
    if (tid < LAYERS) {
        float w00 = W[tid * 4 + 0], w01 = W[tid * 4 + 1];
        float w10 = W[tid * 4 + 2], w11 = W[tid * 4 + 3];
        float b0 = b[tid * 2 + 0], b1 = b[tid * 2 + 1];
        float m = masks[tid];
        float m112 = m * 0x1p112f;
        LayerP p;
        p.w00 = pk2(w00, w00); p.w01 = pk2(w01, w01);
        p.w10 = pk2(w10, w10); p.w11 = pk2(w11, w11);
        p.b0  = pk2(b0, b0);   p.b1  = pk2(b1, b1);
        p.m   = pk2(m, m);     p.m112 = pk2(m112, m112);
        sP[tid] = p;
    }
    if (tid == 0) {
        float s = 0.0f;
        #pragma unroll
        for (int i = 0; i < LAYERS; i++) s += gates[i];
        sG = s;
    }
    __syncthreads();

    const long long gt = (long long)blockIdx.x * TPB + tid;
    const long long f4base = gt * 2;
    if (f4base >= nfloat4) return;
    const bool have2 = (f4base + 1) < nfloat4;

    float4 A = x[f4base];                                    // rows 0,1
    float4 C = have2 ? x[f4base + 1] : make_float4(0,0,0,0); // rows 2,3

    // Row-pair state in packed f32x2:
    u64 Xa = pk2(A.x, A.z), Ya = pk2(A.y, A.w);   // rows 0,1  (exact f32 tanh)
    u64 Xc = pk2(C.x, C.z), Yc = pk2(C.y, C.w);   // rows 2,3  (f16x2 tanh)

    #pragma unroll 4
    for (int l = 0; l < LAYERS; l++) {
        const LayerP p = sP[l];

        // ---- pair A (rows 0,1): exact f32 tanh ----
        u64 argA0 = fma2(p.w00, Xa, fma2(p.w01, Ya, p.b0));
        u64 argA1 = fma2(p.w10, Xa, fma2(p.w11, Ya, p.b1));
        // ---- pair C (rows 2,3): pre-activations ----
        u64 argC0 = fma2(p.w00, Xc, fma2(p.w01, Yc, p.b0));
        u64 argC1 = fma2(p.w10, Xc, fma2(p.w11, Yc, p.b1));

        float a0, a1, b0f, b1f;
        up2(a0, a1, argA0);          // register-pair views, no instruction
        up2(b0f, b1f, argA1);
        float c0, c1, c2, c3;
        up2(c0, c2, argC0);
        up2(c1, c3, argC1);

        // 6 XU ops, independent chains
        float t0 = tanh_f32(a0);
        float t1 = tanh_f32(a1);
        float t2 = tanh_f32(b0f);
        float t3 = tanh_f32(b1f);
        unsigned hX = tanh_h2(pack_h2(c2, c0));  // lo=row2.x-arg, hi=row3.x-arg
        unsigned hY = tanh_h2(pack_h2(c3, c1));  // lo=row2.y-arg, hi=row3.y-arg

        Xa = fma2(p.m, pk2(t0, t1), Xa);
        Ya = fma2(p.m, pk2(t2, t3), Ya);

        // residual: state += (tanh16 * 2^-112) * (m * 2^112)  -- single rounding
        Xc = fma2(p.m112, pk2(mag_lo(hX), mag_hi(hX)), Xc);
        Yc = fma2(p.m112, pk2(mag_lo(hY), mag_hi(hY)), Yc);
    }

    const float g = sG;
    const u64 g2 = pk2(g, g);
    Xa = mul2(g2, Xa); Ya = mul2(g2, Ya);
    Xc = mul2(g2, Xc); Yc = mul2(g2, Yc);

    float x0, x1, y0, y1;
    up2(x0, x1, Xa); up2(y0, y1, Ya);
    out[f4base] = make_float4(x0, y0, x1, y1);
    if (have2) {
        up2(x0, x1, Xc); up2(y0, y1, Yc);
        out[f4base + 1] = make_float4(x0, y0, x1, y1);
    }
}

extern "C" void kernel_launch(void* const* d_in, const int* in_sizes, int n_in,
                              void* d_out, int out_size)
{
    const float4* x     = (const float4*)d_in[0];
    const float*  W     = (const float*) d_in[1];
    const float*  b     = (const float*) d_in[2];
    const float*  masks = (const float*) d_in[3];
    const float*  gates = (const float*) d_in[4];
    float4* out = (float4*)d_out;

    const long long nfloat  = (long long)in_sizes[0];   // BATCH * 2
    const long long nfloat4 = nfloat / 4;               // BATCH / 2
    const long long threads = (nfloat4 + 1) / 2;
    const int blocks = (int)((threads + TPB - 1) / TPB);
    rdb_kernel<<<blocks, TPB>>>(x, W, b, masks, gates, out, nfloat4);
}